// round 4
// baseline (speedup 1.0000x reference)
#include <cuda_runtime.h>

// y[o*48+p, n, m] = sum_i W0[p,i] * t4[o, (n-1)%56, m, i]
// t4[o, n', m, i] = sum_{j,k} xpad[o, j, n', m+k] * W1[j,k,i]  (pad 3 each side, width)
//
// 112 CTAs (one per (o, out-row n), single wave), 512 threads.
// All global loads float4 (1 per thread), 3-acc stage 2, float4 stores in stage 3.

#define NCH 12
#define WID 56
#define XSTRIDE 64          // padded shared row stride; data at offset +4
#define KS 7
#define NI 9
#define NP 48
#define THREADS 512

__global__ __launch_bounds__(THREADS, 1)
void fused_sepconv_kernel(const float* __restrict__ x,
                          const float* __restrict__ W0,
                          const float* __restrict__ W1,
                          float* __restrict__ out) {
    __shared__ alignas(16) float xs[NCH * XSTRIDE];   // 768; data cols [4,60), zeros [0,4)+[60,64)
    __shared__ alignas(16) float w1s[NCH * KS * NI];  // 756
    __shared__ alignas(16) float w0s[NP * NI];        // 432
    __shared__ float t4s[WID * NI];                   // 504, [m][i], stride 9 (conflict-free)

    const int b = blockIdx.x;             // 0..111
    const int o = b / WID;
    const int n = b % WID;
    const int nin = (n + WID - 1) % WID;  // roll(+1) along height
    const int t = threadIdx.x;

    // ---- Phase 1: one float4 global load per thread (max MLP), issued first ----
    // items: [0,168) x-row quads, [168,357) W1 quads, [357,465) W0 quads
    float4 v = make_float4(0.f, 0.f, 0.f, 0.f);
    if (t < 168) {
        int j  = t / 14;
        int q4 = t % 14;
        v = *(const float4*)&x[(((o * NCH + j) * WID + nin) * WID) + 4 * q4];
    } else if (t < 357) {
        v = *(const float4*)&W1[4 * (t - 168)];
    } else if (t < 465) {
        v = *(const float4*)&W0[4 * (t - 357)];
    }

    // Zero the pad columns of xs: 8 per channel row (cols 0..3, 60..63) = 96 slots
    if (t >= 465 && t < 465 + 24) {
        int s = t - 465;                  // 0..23 -> each zeroes a float4 pad block
        int j = s / 2;
        int side = s % 2;
        *(float4*)&xs[j * XSTRIDE + (side ? 60 : 0)] = make_float4(0.f, 0.f, 0.f, 0.f);
    }

    // Scatter loaded quads into shared (aligned float4 stores)
    if (t < 168) {
        int j  = t / 14;
        int q4 = t % 14;
        *(float4*)&xs[j * XSTRIDE + 4 + 4 * q4] = v;
    } else if (t < 357) {
        *(float4*)&w1s[4 * (t - 168)] = v;
    } else if (t < 465) {
        *(float4*)&w0s[4 * (t - 357)] = v;
    }

    __syncthreads();

    // ---- Stage 2: t4[m][i] = sum_{j,k} xs[j][m+k+1] * w1s[(j*7+k)*9 + i] ----
    // 504 threads active; 3 independent accumulators to cut chain depth.
    if (t < WID * NI) {
        const int i = t / WID;            // warp-uniform-ish -> w1s reads broadcast
        const int m = t % WID;
        float a0 = 0.f, a1 = 0.f, a2 = 0.f;
        #pragma unroll
        for (int j = 0; j < 4; ++j) {
            #pragma unroll
            for (int k = 0; k < KS; ++k)
                a0 = fmaf(xs[j * XSTRIDE + m + k + 1], w1s[(j * KS + k) * NI + i], a0);
        }
        #pragma unroll
        for (int j = 4; j < 8; ++j) {
            #pragma unroll
            for (int k = 0; k < KS; ++k)
                a1 = fmaf(xs[j * XSTRIDE + m + k + 1], w1s[(j * KS + k) * NI + i], a1);
        }
        #pragma unroll
        for (int j = 8; j < NCH; ++j) {
            #pragma unroll
            for (int k = 0; k < KS; ++k)
                a2 = fmaf(xs[j * XSTRIDE + m + k + 1], w1s[(j * KS + k) * NI + i], a2);
        }
        t4s[m * NI + i] = a0 + a1 + a2;
    }

    __syncthreads();

    // ---- Stage 3: item = (m-quad, p); 672 items; float4 stores ----
    for (int item = t; item < 14 * NP; item += THREADS) {
        const int mq = item / NP;         // 0..13 (warp-uniform-ish -> t4 reads broadcast)
        const int p  = item % NP;         // 0..47 -> w0 reads stride-9, conflict-free
        const int m0 = 4 * mq;

        float w[NI];
        #pragma unroll
        for (int i = 0; i < NI; ++i) w[i] = w0s[p * NI + i];

        float4 r;
        float* rp = (float*)&r;
        #pragma unroll
        for (int mm = 0; mm < 4; ++mm) {
            const float* t4row = &t4s[(m0 + mm) * NI];
            float acc = 0.f;
            #pragma unroll
            for (int i = 0; i < NI; ++i) acc = fmaf(t4row[i], w[i], acc);
            rp[mm] = acc;
        }
        *(float4*)&out[(((o * NP + p) * WID + n) * WID) + m0] = r;
    }
}

extern "C" void kernel_launch(void* const* d_in, const int* in_sizes, int n_in,
                              void* d_out, int out_size) {
    // Bind inputs by size: x=75264, W0=432, W1=756
    const float* x  = (const float*)d_in[0];
    const float* W0 = (const float*)d_in[1];
    const float* W1 = (const float*)d_in[2];
    for (int i = 0; i < n_in; ++i) {
        if (in_sizes[i] == 75264) x  = (const float*)d_in[i];
        else if (in_sizes[i] == 432) W0 = (const float*)d_in[i];
        else if (in_sizes[i] == 756) W1 = (const float*)d_in[i];
    }
    float* out = (float*)d_out;

    fused_sepconv_kernel<<<2 * WID, THREADS>>>(x, W0, W1, out);
}

// round 5
// speedup vs baseline: 1.3478x; 1.3478x over previous
#include <cuda_runtime.h>

// y[o*48+p, n, m] = sum_i W0[p,i] * t4[o, (n-1)%56, m, i]
// t4[o, n', m, i] = sum_{j,k} xpad[o, j, n', m+k] * W1[j,k,i]  (pad 3 each side, width)
//
// 112 CTAs (one per (o, out-row n), single wave), 512 threads.
// Stage 2: thread = (i, m-pair) -> window-overlap reuse cuts LDS 168->90 per output.

#define NCH 12
#define WID 56
#define XSTRIDE 64          // padded shared row stride; data at offset +4
#define KS 7
#define NI 9
#define NP 48
#define THREADS 512

__global__ __launch_bounds__(THREADS, 1)
void fused_sepconv_kernel(const float* __restrict__ x,
                          const float* __restrict__ W0,
                          const float* __restrict__ W1,
                          float* __restrict__ out) {
    __shared__ alignas(16) float xs[NCH * XSTRIDE];   // 768; data cols [4,60), zeros elsewhere
    __shared__ alignas(16) float w1s[NCH * KS * NI];  // 756
    __shared__ alignas(16) float w0s[NP * NI];        // 432
    __shared__ float t4s[WID * NI];                   // 504, [m][i], stride 9

    const int b = blockIdx.x;             // 0..111
    const int o = b / WID;
    const int n = b % WID;
    const int nin = (n + WID - 1) % WID;  // roll(+1) along height
    const int t = threadIdx.x;

    // ---- Phase 1: one float4 global load per thread, issued first (max MLP) ----
    float4 v = make_float4(0.f, 0.f, 0.f, 0.f);
    if (t < 168) {
        int j  = t / 14;
        int q4 = t % 14;
        v = *(const float4*)&x[(((o * NCH + j) * WID + nin) * WID) + 4 * q4];
    } else if (t < 357) {
        v = *(const float4*)&W1[4 * (t - 168)];
    } else if (t < 465) {
        v = *(const float4*)&W0[4 * (t - 357)];
    }

    // Zero pad columns of xs: cols [0,4) and [60,64) per channel = 24 float4 blocks
    if (t >= 465 && t < 465 + 24) {
        int s = t - 465;
        int j = s / 2;
        int side = s % 2;
        *(float4*)&xs[j * XSTRIDE + (side ? 60 : 0)] = make_float4(0.f, 0.f, 0.f, 0.f);
    }

    if (t < 168) {
        int j  = t / 14;
        int q4 = t % 14;
        *(float4*)&xs[j * XSTRIDE + 4 + 4 * q4] = v;
    } else if (t < 357) {
        *(float4*)&w1s[4 * (t - 168)] = v;
    } else if (t < 465) {
        *(float4*)&w0s[4 * (t - 357)] = v;
    }

    __syncthreads();

    // ---- Stage 2: thread = (m-pair, i); i fast within warp ----
    // outputs m0, m0+1 for one i. Window union per j: xs[m0+1 .. m0+8] (8 loads).
    // w1 loaded once per (j,k), used for both m's.
    if (t < 28 * NI) {                    // 252 threads
        const int i    = t % NI;          // lane-fast: w1 reads consecutive words
        const int pair = t / NI;          // 0..27
        const int m0   = 2 * pair;

        float accA0 = 0.f, accA1 = 0.f;   // output m0 (2 chains)
        float accB0 = 0.f, accB1 = 0.f;   // output m0+1 (2 chains)

        #pragma unroll
        for (int j = 0; j < NCH; ++j) {
            float xw[8];
            #pragma unroll
            for (int kk = 0; kk < 8; ++kk)
                xw[kk] = xs[j * XSTRIDE + m0 + 1 + kk];

            #pragma unroll
            for (int k = 0; k < KS; ++k) {
                const float wv = w1s[(j * KS + k) * NI + i];
                if (k & 1) {
                    accA1 = fmaf(xw[k],     wv, accA1);
                    accB1 = fmaf(xw[k + 1], wv, accB1);
                } else {
                    accA0 = fmaf(xw[k],     wv, accA0);
                    accB0 = fmaf(xw[k + 1], wv, accB0);
                }
            }
        }
        t4s[m0 * NI + i]       = accA0 + accA1;
        t4s[(m0 + 1) * NI + i] = accB0 + accB1;
    }

    __syncthreads();

    // ---- Stage 3: item = (m-quad, p); 672 items; float4 stores ----
    for (int item = t; item < 14 * NP; item += THREADS) {
        const int mq = item / NP;         // warp-uniform-ish -> t4 reads broadcast
        const int p  = item % NP;         // stride-9 w0 reads, conflict-free
        const int m0 = 4 * mq;

        float w[NI];
        #pragma unroll
        for (int i = 0; i < NI; ++i) w[i] = w0s[p * NI + i];

        float4 r;
        float* rp = (float*)&r;
        #pragma unroll
        for (int mm = 0; mm < 4; ++mm) {
            const float* t4row = &t4s[(m0 + mm) * NI];
            float acc = 0.f;
            #pragma unroll
            for (int i = 0; i < NI; ++i) acc = fmaf(t4row[i], w[i], acc);
            rp[mm] = acc;
        }
        *(float4*)&out[(((o * NP + p) * WID + n) * WID) + m0] = r;
    }
}

extern "C" void kernel_launch(void* const* d_in, const int* in_sizes, int n_in,
                              void* d_out, int out_size) {
    // Bind inputs by size: x=75264, W0=432, W1=756
    const float* x  = (const float*)d_in[0];
    const float* W0 = (const float*)d_in[1];
    const float* W1 = (const float*)d_in[2];
    for (int i = 0; i < n_in; ++i) {
        if (in_sizes[i] == 75264) x  = (const float*)d_in[i];
        else if (in_sizes[i] == 432) W0 = (const float*)d_in[i];
        else if (in_sizes[i] == 756) W1 = (const float*)d_in[i];
    }
    float* out = (float*)d_out;

    fused_sepconv_kernel<<<2 * WID, THREADS>>>(x, W0, W1, out);
}